// round 11
// baseline (speedup 1.0000x reference)
#include <cuda_runtime.h>

#define FULL 0xffffffffu
typedef unsigned long long u64;

// ---------------------------------------------------------------------------
// DUAL-ITEM SoA PACKING: each 16-lane group processes TWO batch items.
// Every value is u64 = (item0_float, item1_float); all math is f32x2.
// Warp = 4 items. Full 8-qubit state: slot (lg, j): wire w<4 -> bit w of j,
// wire w>=4 -> bit (w-4) of lg.  Cross phase in phase-twisted b-rep
// (verified R10): b_j = (-i)^pop(j) a_j; lane-ctrl CRX -> real rotations.
// ---------------------------------------------------------------------------

__device__ __forceinline__ u64 pk(float a, float b) {
    u64 r; asm("mov.b64 %0,{%1,%2};" : "=l"(r) : "f"(a), "f"(b)); return r;
}
__device__ __forceinline__ float2 upk(u64 v) {
    float2 r; asm("mov.b64 {%0,%1},%2;" : "=f"(r.x), "=f"(r.y) : "l"(v)); return r;
}
__device__ __forceinline__ u64 dupp(float a) { return pk(a, a); }
__device__ __forceinline__ u64 f2mul(u64 a, u64 b) {
    u64 r; asm("mul.rn.f32x2 %0,%1,%2;" : "=l"(r) : "l"(a), "l"(b)); return r;
}
__device__ __forceinline__ u64 f2fma(u64 a, u64 b, u64 c) {
    u64 r; asm("fma.rn.f32x2 %0,%1,%2,%3;" : "=l"(r) : "l"(a), "l"(b), "l"(c)); return r;
}
__device__ __forceinline__ u64 f2add(u64 a, u64 b) {
    u64 r; asm("add.rn.f32x2 %0,%1,%2;" : "=l"(r) : "l"(a), "l"(b)); return r;
}
__device__ __forceinline__ u64 negp(u64 v) { return v ^ 0x8000000080000000ULL; }

__device__ __forceinline__ u64 shflpx(u64 v, int m) {  // xor-shuffle both halves
    float2 h = upk(v);
    h.x = __shfl_xor_sync(FULL, h.x, m);
    h.y = __shfl_xor_sync(FULL, h.y, m);
    return pk(h.x, h.y);
}
__device__ __forceinline__ u64 shflpi(u64 v, int src) {  // width-16 idx shuffle
    float2 h = upk(v);
    h.x = __shfl_sync(FULL, h.x, src, 16);
    h.y = __shfl_sync(FULL, h.y, src, 16);
    return pk(h.x, h.y);
}

// Segmented butterfly over packed values: reduce 8 u64 over the 16-lane group.
// Lane bits (b3,b2,b1) end with sum of v[4*b3+2*b2+b1] (dup over bit0).
__device__ __forceinline__ u64 segred8p(const u64* v, int lg) {
    const bool b3 = lg & 8, b2 = lg & 4, b1 = lg & 2;
    u64 s0 = b3 ? v[0] : v[4];
    u64 s1 = b3 ? v[1] : v[5];
    u64 s2 = b3 ? v[2] : v[6];
    u64 s3 = b3 ? v[3] : v[7];
    s0 = shflpx(s0, 8); s1 = shflpx(s1, 8); s2 = shflpx(s2, 8); s3 = shflpx(s3, 8);
    u64 n0 = f2add(b3 ? v[4] : v[0], s0);
    u64 n1 = f2add(b3 ? v[5] : v[1], s1);
    u64 n2 = f2add(b3 ? v[6] : v[2], s2);
    u64 n3 = f2add(b3 ? v[7] : v[3], s3);
    u64 t0 = b2 ? n0 : n2;
    u64 t1 = b2 ? n1 : n3;
    t0 = shflpx(t0, 4); t1 = shflpx(t1, 4);
    n0 = f2add(b2 ? n2 : n0, t0);
    n1 = f2add(b2 ? n3 : n1, t1);
    u64 u0 = b1 ? n0 : n1;
    u0 = shflpx(u0, 2);
    n0 = f2add(b1 ? n1 : n0, u0);
    n0 = f2add(n0, shflpx(n0, 1));
    return n0;
}

// packed rxmix: newR = C*R + S*tI ; newI = C*I - S*tR
__device__ __forceinline__ void rxp(u64& R, u64& I, u64 tR, u64 tI, u64 C, u64 S, u64 nS) {
    R = f2fma(S, tI, f2mul(C, R));
    I = f2fma(nS, tR, f2mul(C, I));
}

// packed general unitary [[u00,u01],[-conj(u01),conj(u00)]], own bit b
// newR = cx*R - cy'*I + dx'*tR - dy*tI ; newI = cx*I + cy'*R + dx'*tI + dy*tR
__device__ __forceinline__ void genp(u64& R, u64& I, u64 tR, u64 tI,
                                     u64 CX, u64 CY, u64 DX, u64 DY, int b) {
    u64 cy = b ? negp(CY) : CY;
    u64 dx = b ? negp(DX) : DX;
    u64 nR = f2fma(CX, R, f2fma(negp(cy), I, f2fma(dx, tR, f2mul(negp(DY), tI))));
    u64 nI = f2fma(CX, I, f2fma(cy, R, f2fma(dx, tI, f2mul(DY, tR))));
    R = nR; I = nI;
}

// fused U = GEN @ RX(theta) with packed per-item (c,s):
// u00 = (c*gx + s*gw, c*gy - s*gz), u01 = (c*gz + s*gy, c*gw - s*gx)
__device__ __forceinline__ void fusep(float4 g, u64 C, u64 S,
                                      u64& U0R, u64& U0I, u64& U1R, u64& U1I) {
    u64 nS = negp(S);
    U0R = f2fma(C, dupp(g.x), f2mul(S, dupp(g.w)));
    U0I = f2fma(C, dupp(g.y), f2mul(nS, dupp(g.z)));
    U1R = f2fma(C, dupp(g.z), f2mul(S, dupp(g.y)));
    U1I = f2fma(C, dupp(g.w), f2mul(nS, dupp(g.x)));
}

// ---------------------------------------------------------------------------

__global__ void __launch_bounds__(64, 4)
qa_fused(const float* __restrict__ x_text, const float* __restrict__ x_image,
         const float* __restrict__ W_text, const float* __restrict__ b_text,
         const float* __restrict__ W_image, const float* __restrict__ b_image,
         const float* __restrict__ qr, const float* __restrict__ qc,
         const float* __restrict__ kr, const float* __restrict__ kc,
         const float* __restrict__ vr, const float* __restrict__ vc,
         const float* __restrict__ cr, const float* __restrict__ cc,
         const float* __restrict__ cc2, const float* __restrict__ gates,
         float* __restrict__ out, int B, int IN) {
    __shared__ float4 sf[28];
    __shared__ float2 scs[40];
    __shared__ float sgates[4];
    __shared__ float4 szm[4];  // (p, m.x, m.y, r)
    __shared__ float2 sn[4];   // (n.x, n.y)

    for (int t = threadIdx.x; t < 76; t += blockDim.x) {
        if (t < 28) {
            int grp = t >> 2, i = t & 3;
            float a = 0.f, b = 0.f, c = 0.f;
            switch (grp) {
                case 0: a = qr[3 * i];      b = qr[3 * i + 1];      c = qr[3 * i + 2];      break;
                case 1: a = qr[12 + 3 * i]; b = qr[12 + 3 * i + 1]; c = qr[12 + 3 * i + 2]; break;
                case 2: a = kr[3 * i];      b = kr[3 * i + 1];      c = kr[3 * i + 2];      break;
                case 3: a = kr[12 + 3 * i]; b = kr[12 + 3 * i + 1]; c = kr[12 + 3 * i + 2]; break;
                case 4: a = cr[3 * i];      b = cr[3 * i + 1];      c = cr[3 * i + 2];      break;
                case 5: a = vr[3 * i];      b = vr[3 * i + 1];      c = vr[3 * i + 2];      break;
                case 6: a = vr[12 + 3 * i]; b = vr[12 + 3 * i + 1]; c = vr[12 + 3 * i + 2]; break;
            }
            float cb = cosf(0.5f * b), sb = sinf(0.5f * b);
            float sum = 0.5f * (a + c), dif = 0.5f * (a - c);
            sf[t] = make_float4(cb * cosf(sum), -cb * sinf(sum),
                                sb * sinf(dif), -sb * cosf(dif));
        } else if (t < 68) {
            int u = t - 28;
            float p;
            if (u < 8) p = qc[u];
            else if (u < 16) p = kc[u - 8];
            else if (u < 24) p = cc[u - 16];
            else if (u < 32) p = cc2[u - 24];
            else p = vc[u - 32];
            float s, c;
            sincosf(0.5f * p, &s, &c);
            scs[u] = make_float2(c, s);
        } else if (t < 72) {
            sgates[t - 68] = gates[t - 68];
        } else {
            int i = t - 72;
            float aa = cr[3 * i], b = cr[3 * i + 1], c = cr[3 * i + 2];
            float cb = cosf(0.5f * b), sb = sinf(0.5f * b);
            float sum = 0.5f * (aa + c), dif = 0.5f * (aa - c);
            float alx = cb * cosf(sum), aly = -cb * sinf(sum);
            float bex = sb * sinf(dif), bey = -sb * cosf(dif);
            float p = alx * alx + aly * aly - bex * bex - bey * bey;
            float mx = 2.f * (alx * bex + aly * bey);
            float my = 2.f * (alx * bey - aly * bex);
            float r = -2.f * (alx * bex - aly * bey);
            float nx = (alx * alx - aly * aly) - (bex * bex - bey * bey);
            float ny = -2.f * alx * aly - 2.f * bex * bey;
            szm[i] = make_float4(p, mx, my, r);
            sn[i] = make_float2(nx, ny);
        }
    }
    __syncthreads();

    const int lane = threadIdx.x & 31;
    const int half = lane >> 4;
    const int lg = lane & 15;
    const int wsel = ((lg >> 2) & 1) * 2 + ((lg >> 1) & 1);
    const int gw = (int)((blockIdx.x * blockDim.x + threadIdx.x) >> 5);
    const int it0 = gw * 4 + half * 2;
    const int it1 = it0 + 1;
    const int ic0 = it0 < B ? it0 : (B - 1);
    const int ic1 = it1 < B ? it1 : (B - 1);

    // ---- projections: scalar MACs for both items, packed segred ----
    u64 CQ[4], SQ[4], CK[4], SK[4];   // packed per-item (cos,sin) of embeddings
    {
        const float2* xt0 = (const float2*)(x_text + (long)ic0 * IN);
        const float2* xt1 = (const float2*)(x_text + (long)ic1 * IN);
        const float2* xi0 = (const float2*)(x_image + (long)ic0 * IN);
        const float2* xi1 = (const float2*)(x_image + (long)ic1 * IN);
        const int hin = IN >> 1;
        float p0[8] = {0,0,0,0,0,0,0,0}, p1[8] = {0,0,0,0,0,0,0,0};
#define PROJ_STEP(KK) { const int k = lg + (KK);                              \
        float2 a0 = __ldg(&xt0[k]), a1 = __ldg(&xt1[k]);                      \
        float2 b0 = __ldg(&xi0[k]), b1 = __ldg(&xi1[k]);                      \
        _Pragma("unroll")                                                     \
        for (int r = 0; r < 4; r++) {                                         \
            float2 wa = __ldg((const float2*)(W_text + r * IN) + k);          \
            float2 wb = __ldg((const float2*)(W_image + r * IN) + k);         \
            p0[r]     += a0.x * wa.x + a0.y * wa.y;                           \
            p1[r]     += a1.x * wa.x + a1.y * wa.y;                           \
            p0[4 + r] += b0.x * wb.x + b0.y * wb.y;                           \
            p1[4 + r] += b1.x * wb.x + b1.y * wb.y;                           \
        } }
        if (hin == 48) { PROJ_STEP(0) PROJ_STEP(16) PROJ_STEP(32) }
        else {
            for (int k0 = 0; k0 < hin; k0 += 16) {
                if (lg + k0 < hin) { PROJ_STEP(k0) }
            }
        }
#undef PROJ_STEP
        u64 pv[8];
#pragma unroll
        for (int t = 0; t < 8; t++) pv[t] = pk(p0[t], p1[t]);
        u64 xv = segred8p(pv, lg);
        const bool gk = lg & 8;
        float bias = __ldg((gk ? b_image : b_text) + wsel);
        xv = f2add(xv, dupp(bias));
        float2 x2 = upk(xv);
        float s0, c0, s1, c1;
        __sincosf(0.5f * x2.x, &s0, &c0);
        __sincosf(0.5f * x2.y, &s1, &c1);
        u64 cp = pk(c0, c1), sp = pk(s0, s1);
#pragma unroll
        for (int i = 0; i < 4; i++) {
            CQ[i] = shflpi(cp, 2 * i);
            SQ[i] = shflpi(sp, 2 * i);
            CK[i] = shflpi(cp, 8 | (2 * i));
            SK[i] = shflpi(sp, 8 | (2 * i));
        }
    }

    // ---- product phase: three interleaved 16-amp rings (SoA packed) ----
    u64 Rq = (lg == 0) ? dupp(1.f) : 0ULL, Iq = 0ULL;
    u64 Rk = Rq, Ik = 0ULL, Rv = Rq, Iv = 0ULL;

#pragma unroll
    for (int i = 0; i < 4; i++) {  // L1 with fused data RX
        u64 q0R, q0I, q1R, q1I, k0R, k0I, k1R, k1I, v0R, v0I, v1R, v1I;
        fusep(sf[i],      CQ[i], SQ[i], q0R, q0I, q1R, q1I);
        fusep(sf[8 + i],  CK[i], SK[i], k0R, k0I, k1R, k1I);
        fusep(sf[20 + i], CK[i], SK[i], v0R, v0I, v1R, v1I);
        const int b = (lg >> i) & 1;
        const int m = 1 << i;
        u64 tqR = shflpx(Rq, m), tqI = shflpx(Iq, m);
        u64 tkR = shflpx(Rk, m), tkI = shflpx(Ik, m);
        u64 tvR = shflpx(Rv, m), tvI = shflpx(Iv, m);
        genp(Rq, Iq, tqR, tqI, q0R, q0I, q1R, q1I, b);
        genp(Rk, Ik, tkR, tkI, k0R, k0I, k1R, k1I, b);
        genp(Rv, Iv, tvR, tvI, v0R, v0I, v1R, v1I, b);
    }
#pragma unroll
    for (int i = 0; i < 4; i++) {  // CRX rings (branchless coefficient select)
        const int m = 1 << ((i + 1) & 3);
        const bool p = (lg >> i) & 1;
        u64 Cq = dupp(p ? scs[i].x : 1.f),      Sq = dupp(p ? scs[i].y : 0.f);
        u64 Ck = dupp(p ? scs[8 + i].x : 1.f),  Sk = dupp(p ? scs[8 + i].y : 0.f);
        u64 Cv = dupp(p ? scs[32 + i].x : 1.f), Sv = dupp(p ? scs[32 + i].y : 0.f);
        u64 tqR = shflpx(Rq, m), tqI = shflpx(Iq, m);
        u64 tkR = shflpx(Rk, m), tkI = shflpx(Ik, m);
        u64 tvR = shflpx(Rv, m), tvI = shflpx(Iv, m);
        rxp(Rq, Iq, tqR, tqI, Cq, Sq, negp(Sq));
        rxp(Rk, Ik, tkR, tkI, Ck, Sk, negp(Sk));
        rxp(Rv, Iv, tvR, tvI, Cv, Sv, negp(Sv));
    }
#pragma unroll
    for (int i = 0; i < 4; i++) {  // IsingXX rings
        const int m = (1 << i) | (1 << ((i + 1) & 3));
        u64 Cq = dupp(scs[4 + i].x),  Sq = dupp(scs[4 + i].y);
        u64 Ck = dupp(scs[12 + i].x), Sk = dupp(scs[12 + i].y);
        u64 Cv = dupp(scs[36 + i].x), Sv = dupp(scs[36 + i].y);
        u64 tqR = shflpx(Rq, m), tqI = shflpx(Iq, m);
        u64 tkR = shflpx(Rk, m), tkI = shflpx(Ik, m);
        u64 tvR = shflpx(Rv, m), tvI = shflpx(Iv, m);
        rxp(Rq, Iq, tqR, tqI, Cq, Sq, negp(Sq));
        rxp(Rk, Ik, tkR, tkI, Ck, Sk, negp(Sk));
        rxp(Rv, Iv, tvR, tvI, Cv, Sv, negp(Sv));
    }
#pragma unroll
    for (int i = 0; i < 4; i++) {  // L2 rot layers (constant gates)
        const int b = (lg >> i) & 1;
        const int m = 1 << i;
        float4 uq = sf[4 + i], uk = sf[12 + i], uv = sf[24 + i];
        u64 tqR = shflpx(Rq, m), tqI = shflpx(Iq, m);
        u64 tkR = shflpx(Rk, m), tkI = shflpx(Ik, m);
        u64 tvR = shflpx(Rv, m), tvI = shflpx(Iv, m);
        genp(Rq, Iq, tqR, tqI, dupp(uq.x), dupp(uq.y), dupp(uq.z), dupp(uq.w), b);
        genp(Rk, Ik, tkR, tkI, dupp(uk.x), dupp(uk.y), dupp(uk.z), dupp(uk.w), b);
        genp(Rv, Iv, tvR, tvI, dupp(uv.x), dupp(uv.y), dupp(uv.z), dupp(uv.w), b);
    }

    // ---- assemble full state in b-rep: sigma twist on vq, then cmul ----
    u64 AR[16], AI[16];
    {
        int pop = __popc(lg);
        bool p1 = pop & 1, p2 = pop & 2;
        u64 Rt = p1 ? Iq : Rq;
        u64 It = p1 ? negp(Rq) : Iq;
        u64 Rq2 = p2 ? negp(Rt) : Rt;
        u64 Iq2 = p2 ? negp(It) : It;
#pragma unroll
        for (int j = 0; j < 16; j++) {
            u64 qR = shflpi(Rq2, j), qI = shflpi(Iq2, j);
            AR[j] = f2fma(qR, Rk, negp(f2mul(qI, Ik)));
            AI[j] = f2fma(qR, Ik, f2mul(qI, Rk));
        }
    }

    // ---- cross entanglers in b-rep (SoA packed) ----
    // CRX(i,4+i): local ctrl -> lane target (complex rxmix)
#pragma unroll
    for (int i = 0; i < 4; i++) {
        u64 C = dupp(scs[16 + i].x), S = dupp(scs[16 + i].y), nS = negp(S);
        const int ml = 1 << i;
#pragma unroll
        for (int j = 0; j < 16; j++)
            if ((j >> i) & 1) {
                u64 tR = shflpx(AR[j], ml), tI = shflpx(AI[j], ml);
                AR[j] = f2fma(S, tI, f2mul(C, AR[j]));
                AI[j] = f2fma(nS, tR, f2mul(C, AI[j]));
            }
    }
    // CRX(4+i,i): lane ctrl -> local target (REAL rotation in b-rep)
#pragma unroll
    for (int i = 0; i < 4; i++) {
        const bool e = (lg >> i) & 1;
        u64 C = dupp(e ? scs[20 + i].x : 1.f), S = dupp(e ? scs[20 + i].y : 0.f);
        u64 nS = negp(S);
        const int m = 1 << i;
#pragma unroll
        for (int j = 0; j < 16; j++)
            if (!(j & m)) {
                int j2 = j | m;
                u64 R0 = AR[j], I0 = AI[j], R1 = AR[j2], I1 = AI[j2];
                AR[j]  = f2fma(S, R1, f2mul(C, R0));
                AI[j]  = f2fma(S, I1, f2mul(C, I0));
                AR[j2] = f2fma(nS, R0, f2mul(C, R1));
                AI[j2] = f2fma(nS, I0, f2mul(C, I1));
            }
    }
    // CRX2(i, ((i+1)&3)+4): local ctrl -> lane target
#pragma unroll
    for (int i = 0; i < 4; i++) {
        u64 C = dupp(scs[24 + i].x), S = dupp(scs[24 + i].y), nS = negp(S);
        const int ml = 1 << ((i + 1) & 3);
#pragma unroll
        for (int j = 0; j < 16; j++)
            if ((j >> i) & 1) {
                u64 tR = shflpx(AR[j], ml), tI = shflpx(AI[j], ml);
                AR[j] = f2fma(S, tI, f2mul(C, AR[j]));
                AI[j] = f2fma(nS, tR, f2mul(C, AI[j]));
            }
    }
    // CRX2(4+i, (i+1)&3): lane ctrl -> local target (real rotation)
#pragma unroll
    for (int i = 0; i < 4; i++) {
        const bool e = (lg >> i) & 1;
        u64 C = dupp(e ? scs[28 + i].x : 1.f), S = dupp(e ? scs[28 + i].y : 0.f);
        u64 nS = negp(S);
        const int m = 1 << ((i + 1) & 3);
#pragma unroll
        for (int j = 0; j < 16; j++)
            if (!(j & m)) {
                int j2 = j | m;
                u64 R0 = AR[j], I0 = AI[j], R1 = AR[j2], I1 = AI[j2];
                AR[j]  = f2fma(S, R1, f2mul(C, R0));
                AI[j]  = f2fma(S, I1, f2mul(C, I0));
                AR[j2] = f2fma(nS, R0, f2mul(C, R1));
                AI[j2] = f2fma(nS, I0, f2mul(C, I1));
            }
    }
    // all 4 CNOT(i,4+i): one dynamic-src shuffle stage (width-16)
#pragma unroll
    for (int j = 0; j < 16; j++) {
        AR[j] = shflpi(AR[j], lg ^ j);
        AI[j] = shflpi(AI[j], lg ^ j);
    }
    // all 4 CNOT(4+i,i): FREE via basis relabel (slot j holds basis j^lg).

    // ---- measurement (final rot folded into observables; b-rep corrected) ----
    u64 CC0[4], SS0[4];
    {
        u64 nj[16];
#pragma unroll
        for (int j = 0; j < 16; j++)
            nj[j] = f2fma(AR[j], AR[j], f2mul(AI[j], AI[j]));

        u64 acc[8];
#pragma unroll
        for (int w = 0; w < 4; w++) {
            const int m = 1 << w;
            const float4 zm = szm[w];
            const float2 nn = sn[w];
            const float sgn = ((lg >> w) & 1) ? -1.f : 1.f;
            u64 zD = dupp(zm.x * sgn), znR = dupp(-2.f * zm.y), znI = dupp(-2.f * zm.z * sgn);
            u64 xD = dupp(zm.w * sgn), xnR = dupp(-2.f * nn.x), xnI = dupp(-2.f * nn.y * sgn);
            u64 z = 0ULL, x = 0ULL;
#pragma unroll
            for (int j = 0; j < 16; j++) {
                if (j & m) continue;
                u64 R0 = AR[j], I0 = AI[j], R1 = AR[j | m], I1 = AI[j | m];
                u64 D = f2add(nj[j], negp(nj[j | m]));
                u64 Rb = f2fma(R0, R1, f2mul(I0, I1));
                u64 Ib = f2fma(R0, I1, negp(f2mul(I0, R1)));
                z = f2fma(zD, D, z); z = f2fma(znR, Ib, z); z = f2fma(znI, Rb, z);
                x = f2fma(xD, D, x); x = f2fma(xnR, Ib, x); x = f2fma(xnI, Rb, x);
            }
            acc[w] = z;
            acc[4 + w] = x;
        }
        u64 S = segred8p(acc, lg);
        u64 other = shflpx(S, 8);
        float2 S2 = upk(S), O2 = upk(other);
        float amp0 = sqrtf(S2.x * S2.x + O2.x * O2.x);
        float amp1 = sqrtf(S2.y * S2.y + O2.y * O2.y);
        float sg = sgates[wsel];
        float a0 = tanhf(amp0) * sg, a1 = tanhf(amp1) * sg;
        float s0, c0, s1, c1;
        __sincosf(0.5f * a0, &s0, &c0);
        __sincosf(0.5f * a1, &s1, &c1);
        u64 cp = pk(c0, c1), sp = pk(s0, s1);
#pragma unroll
        for (int i = 0; i < 4; i++) {
            CC0[i] = shflpi(cp, 2 * i);
            SS0[i] = shflpi(sp, 2 * i);
        }
    }

    // ---- value tail: amp-RX fused pairwise (a-rep SoA) ----
    {
        {   // wires 0,1 (masks 1,2)
            u64 AB = f2mul(CC0[0], CC0[1]), AsB = f2mul(CC0[0], SS0[1]);
            u64 sAB = f2mul(SS0[0], CC0[1]), ss = f2mul(SS0[0], SS0[1]);
            u64 nsAB = negp(sAB), nAsB = negp(AsB), nss = negp(ss);
            u64 t0R = shflpx(Rv, 1), t0I = shflpx(Iv, 1);
            u64 t1R = shflpx(Rv, 2), t1I = shflpx(Iv, 2);
            u64 t2R = shflpx(Rv, 3), t2I = shflpx(Iv, 3);
            u64 nR = f2fma(AB, Rv, f2fma(sAB, t0I, f2fma(AsB, t1I, f2mul(nss, t2R))));
            u64 nI = f2fma(AB, Iv, f2fma(nsAB, t0R, f2fma(nAsB, t1R, f2mul(nss, t2I))));
            Rv = nR; Iv = nI;
        }
        {   // wires 2,3 (masks 4,8)
            u64 AB = f2mul(CC0[2], CC0[3]), AsB = f2mul(CC0[2], SS0[3]);
            u64 sAB = f2mul(SS0[2], CC0[3]), ss = f2mul(SS0[2], SS0[3]);
            u64 nsAB = negp(sAB), nAsB = negp(AsB), nss = negp(ss);
            u64 t0R = shflpx(Rv, 4), t0I = shflpx(Iv, 4);
            u64 t1R = shflpx(Rv, 8), t1I = shflpx(Iv, 8);
            u64 t2R = shflpx(Rv, 12), t2I = shflpx(Iv, 12);
            u64 nR = f2fma(AB, Rv, f2fma(sAB, t0I, f2fma(AsB, t1I, f2mul(nss, t2R))));
            u64 nI = f2fma(AB, Iv, f2fma(nsAB, t0R, f2fma(nAsB, t1R, f2mul(nss, t2I))));
            Rv = nR; Iv = nI;
        }
    }
    // CNOT ring folded into measurement via basis permutation pi
    int pi = lg;
    pi ^= (pi & 1) << 1;
    pi ^= ((pi >> 1) & 1) << 2;
    pi ^= ((pi >> 2) & 1) << 3;
    pi ^= (pi >> 3) & 1;

    // ---- final measurement: packed segred + scatter store (2 items) ----
    {
        u64 ov[8];
        u64 nv = f2fma(Rv, Rv, f2mul(Iv, Iv));
        u64 nvn = negp(nv);
#pragma unroll
        for (int w = 0; w < 4; w++) ov[w] = ((pi >> w) & 1) ? nvn : nv;
#pragma unroll
        for (int w = 0; w < 4; w++) {
            int r = pi ^ (1 << w);
            r ^= (r >> 3) & 1;
            r ^= ((r >> 2) & 1) << 3;
            r ^= ((r >> 1) & 1) << 2;
            r ^= (r & 1) << 1;
            u64 tR = shflpi(Rv, r), tI = shflpi(Iv, r);
            ov[4 + w] = f2fma(Rv, tR, f2mul(Iv, tI));
        }
        u64 oS = segred8p(ov, lg);
        float2 o2 = upk(oS);
        const int oidx = ((lg >> 3) & 1) * 4 + wsel;
        if (!(lg & 1)) {
            if (it0 < B) out[(long)it0 * 8 + oidx] = o2.x;
            if (it1 < B) out[(long)it1 * 8 + oidx] = o2.y;
        }
    }
}

// ---------------------------------------------------------------------------

extern "C" void kernel_launch(void* const* d_in, const int* in_sizes, int n_in,
                              void* d_out, int out_size) {
    const float* x_text  = (const float*)d_in[0];
    const float* x_image = (const float*)d_in[1];
    const float* W_text  = (const float*)d_in[2];
    const float* b_text  = (const float*)d_in[3];
    const float* W_image = (const float*)d_in[4];
    const float* b_image = (const float*)d_in[5];
    const float* q_rot   = (const float*)d_in[6];
    const float* q_crx   = (const float*)d_in[7];
    const float* k_rot   = (const float*)d_in[8];
    const float* k_crx   = (const float*)d_in[9];
    const float* v_rot   = (const float*)d_in[10];
    const float* v_crx   = (const float*)d_in[11];
    const float* c_rot   = (const float*)d_in[12];
    const float* c_crx   = (const float*)d_in[13];
    const float* c_crx2  = (const float*)d_in[14];
    const float* gates   = (const float*)d_in[15];

    int IN = in_sizes[2] / 4;   // W_text is [4, IN]
    int B  = in_sizes[0] / IN;  // x_text is [B, IN]

    int nwarps = (B + 3) / 4;   // 4 items per warp (2 per half-warp group)
    int threads = 64;
    int blocks = (nwarps * 32 + threads - 1) / threads;
    qa_fused<<<blocks, threads>>>(x_text, x_image, W_text, b_text, W_image, b_image,
                                  q_rot, q_crx, k_rot, k_crx, v_rot, v_crx,
                                  c_rot, c_crx, c_crx2, gates,
                                  (float*)d_out, B, IN);
}